// round 2
// baseline (speedup 1.0000x reference)
#include <cuda_runtime.h>
#include <cuda_bf16.h>
#include <math.h>

// Problem constants
#define BB 2
#define TT 1024
#define DD 1024
#define HH 16
#define LL 6
#define DHH 64
#define DFFF 2048
#define MROWS (BB*TT)   // 2048

// ---------------- scratch (device globals: no allocation allowed) ----------
__device__ float g_x  [MROWS * DD];     // residual stream
__device__ float g_h  [MROWS * DD];     // LN output
__device__ float g_qkv[MROWS * 3 * DD]; // qkv
__device__ float g_o  [MROWS * DD];     // attention output
__device__ float g_a  [MROWS * DFFF];   // ffn activation

// ---------------- embedding -------------------------------------------------
__global__ void embed_kernel(const int* __restrict__ ids,
                             const float* __restrict__ tok,
                             const float* __restrict__ pos,
                             float* __restrict__ x)
{
    int idx = blockIdx.x * blockDim.x + threadIdx.x; // over B*T*D = 2M
    if (idx >= MROWS * DD) return;
    int d  = idx & (DD - 1);
    int bt = idx / DD;
    int t  = bt & (TT - 1);
    x[idx] = tok[(size_t)ids[bt] * DD + d] + pos[t * DD + d];
}

// ---------------- layernorm (biased var, eps 1e-5) --------------------------
__global__ void ln_kernel(const float* __restrict__ x,
                          const float* __restrict__ s,
                          const float* __restrict__ b,
                          float* __restrict__ y)
{
    int row = blockIdx.x;
    const float* xr = x + (size_t)row * DD;
    float*       yr = y + (size_t)row * DD;

    float sum = 0.f, sq = 0.f;
    // 256 threads, 4 floats each via float4
    int c4 = threadIdx.x; // 0..255, each owns one float4 of 256
    float4 v = ((const float4*)xr)[c4];
    sum = v.x + v.y + v.z + v.w;
    sq  = v.x*v.x + v.y*v.y + v.z*v.z + v.w*v.w;

    // block reduce
    __shared__ float rs[8], rq[8];
    for (int o = 16; o > 0; o >>= 1) {
        sum += __shfl_xor_sync(0xffffffffu, sum, o);
        sq  += __shfl_xor_sync(0xffffffffu, sq,  o);
    }
    int wid = threadIdx.x >> 5;
    if ((threadIdx.x & 31) == 0) { rs[wid] = sum; rq[wid] = sq; }
    __syncthreads();
    if (threadIdx.x < 8) { sum = rs[threadIdx.x]; sq = rq[threadIdx.x]; }
    else                 { sum = 0.f; sq = 0.f; }
    if (threadIdx.x < 32) {
        for (int o = 4; o > 0; o >>= 1) {
            sum += __shfl_xor_sync(0xffffffffu, sum, o);
            sq  += __shfl_xor_sync(0xffffffffu, sq,  o);
        }
    }
    __shared__ float s_mean, s_inv;
    if (threadIdx.x == 0) {
        float mean = sum * (1.f / DD);
        float var  = sq * (1.f / DD) - mean * mean;
        s_mean = mean;
        s_inv  = rsqrtf(var + 1e-5f);
    }
    __syncthreads();
    float mean = s_mean, inv = s_inv;

    float4 sv = ((const float4*)s)[c4];
    float4 bv = ((const float4*)b)[c4];
    float4 ov;
    ov.x = (v.x - mean) * inv * sv.x + bv.x;
    ov.y = (v.y - mean) * inv * sv.y + bv.y;
    ov.z = (v.z - mean) * inv * sv.z + bv.z;
    ov.w = (v.w - mean) * inv * sv.w + bv.w;
    ((float4*)yr)[c4] = ov;
}

// ---------------- fp32 SIMT GEMM: C = epilogue(A[MxK] @ B[KxN]) -------------
// EPI: 0 = store, 1 = X + A@B (residual add), 2 = exact GELU(A@B)
template<int EPI>
__global__ __launch_bounds__(256) void gemm128(
    const float* __restrict__ A, const float* __restrict__ B,
    const float* __restrict__ X, float* __restrict__ C,
    int M, int N, int K)
{
    const int BK = 8, TM = 8, TN = 8;
    __shared__ float As[BK][128];
    __shared__ float Bs[BK][128];

    int tid = threadIdx.x;
    int tr = tid >> 4, tc = tid & 15;           // 16x16 thread grid
    float acc[TM][TN] = {};

    int aRow = tid >> 1;                        // 0..127
    int aCol = (tid & 1) * 4;                   // 0 or 4
    int bRow = tid >> 5;                        // 0..7
    int bCol = (tid & 31) * 4;                  // 0..124 step 4

    const float* Ab = A + (size_t)(blockIdx.y * 128) * K;
    const float* Bb = B + blockIdx.x * 128;

    for (int k0 = 0; k0 < K; k0 += BK) {
        float4 av = *(const float4*)(Ab + (size_t)aRow * K + k0 + aCol);
        As[aCol + 0][aRow] = av.x;
        As[aCol + 1][aRow] = av.y;
        As[aCol + 2][aRow] = av.z;
        As[aCol + 3][aRow] = av.w;
        float4 bv = *(const float4*)(Bb + (size_t)(k0 + bRow) * N + bCol);
        *(float4*)&Bs[bRow][bCol] = bv;
        __syncthreads();
        #pragma unroll
        for (int k = 0; k < BK; k++) {
            float ra[TM], rb[TN];
            #pragma unroll
            for (int i = 0; i < TM; i++) ra[i] = As[k][tr * TM + i];
            #pragma unroll
            for (int j = 0; j < TN; j++) rb[j] = Bs[k][tc * TN + j];
            #pragma unroll
            for (int i = 0; i < TM; i++)
                #pragma unroll
                for (int j = 0; j < TN; j++)
                    acc[i][j] = fmaf(ra[i], rb[j], acc[i][j]);
        }
        __syncthreads();
    }

    int row0 = blockIdx.y * 128 + tr * TM;
    int col0 = blockIdx.x * 128 + tc * TN;
    #pragma unroll
    for (int i = 0; i < TM; i++) {
        #pragma unroll
        for (int j = 0; j < TN; j++) {
            float v = acc[i][j];
            if (EPI == 1) v += X[(size_t)(row0 + i) * N + col0 + j];
            if (EPI == 2) v = 0.5f * v * (1.f + erff(v * 0.70710678118654752f));
            C[(size_t)(row0 + i) * N + col0 + j] = v;
        }
    }
}

// ---------------- flash attention (causal, DH=64, 64-row tiles) -------------
#define ALD 65
#define ATTN_SMEM ((4 * 64 * ALD + 3 * 64) * (int)sizeof(float))

__global__ __launch_bounds__(256) void attn_kernel(const float* __restrict__ qkv,
                                                   float* __restrict__ o)
{
    extern __shared__ float sm[];
    float* Qs   = sm;
    float* Ks   = Qs + 64 * ALD;
    float* Vs   = Ks + 64 * ALD;
    float* Ss   = Vs + 64 * ALD;
    float* Mrow = Ss + 64 * ALD;
    float* Lrow = Mrow + 64;
    float* Arow = Lrow + 64;

    int qt = blockIdx.x;            // 0..15 (q tile)
    int bh = blockIdx.y;            // 0..31
    int b = bh / HH, h = bh % HH;
    int tid = threadIdx.x;
    int ty = tid >> 4, tx = tid & 15;
    int r0 = ty * 4, c0 = tx * 4;

    // load Q tile
    for (int e = tid; e < 64 * 64; e += 256) {
        int r = e >> 6, c = e & 63;
        Qs[r * ALD + c] = qkv[(size_t)(b * TT + qt * 64 + r) * 3 * DD + h * DHH + c];
    }
    if (tid < 64) { Mrow[tid] = -1e30f; Lrow[tid] = 0.f; }

    float accO[4][4] = {};
    const float scale = 0.125f; // 1/sqrt(64)

    for (int jt = 0; jt <= qt; jt++) {
        __syncthreads();
        for (int e = tid; e < 64 * 64; e += 256) {
            int r = e >> 6, c = e & 63;
            size_t rowoff = (size_t)(b * TT + jt * 64 + r) * 3 * DD;
            Ks[r * ALD + c] = qkv[rowoff + DD     + h * DHH + c];
            Vs[r * ALD + c] = qkv[rowoff + 2 * DD + h * DHH + c];
        }
        __syncthreads();

        // S = Q K^T (4x4 per thread)
        float s[4][4] = {};
        #pragma unroll 4
        for (int k = 0; k < 64; k++) {
            float qv[4], kv[4];
            #pragma unroll
            for (int i = 0; i < 4; i++) qv[i] = Qs[(r0 + i) * ALD + k];
            #pragma unroll
            for (int j = 0; j < 4; j++) kv[j] = Ks[(c0 + j) * ALD + k];
            #pragma unroll
            for (int i = 0; i < 4; i++)
                #pragma unroll
                for (int j = 0; j < 4; j++)
                    s[i][j] = fmaf(qv[i], kv[j], s[i][j]);
        }
        bool diag = (jt == qt);
        #pragma unroll
        for (int i = 0; i < 4; i++)
            #pragma unroll
            for (int j = 0; j < 4; j++) {
                float v = s[i][j] * scale;
                if (diag && (c0 + j) > (r0 + i)) v = -1e30f;
                Ss[(r0 + i) * ALD + c0 + j] = v;
            }
        __syncthreads();

        // online softmax: 4 threads per row
        int rr = tid >> 2, sub = tid & 3;
        float mloc = -1e30f;
        for (int c = sub * 16; c < sub * 16 + 16; c++)
            mloc = fmaxf(mloc, Ss[rr * ALD + c]);
        mloc = fmaxf(mloc, __shfl_xor_sync(0xffffffffu, mloc, 1));
        mloc = fmaxf(mloc, __shfl_xor_sync(0xffffffffu, mloc, 2));
        float mold = Mrow[rr];
        float mnew = fmaxf(mold, mloc);
        float sloc = 0.f;
        for (int c = sub * 16; c < sub * 16 + 16; c++) {
            float p = __expf(Ss[rr * ALD + c] - mnew);
            Ss[rr * ALD + c] = p;
            sloc += p;
        }
        sloc += __shfl_xor_sync(0xffffffffu, sloc, 1);
        sloc += __shfl_xor_sync(0xffffffffu, sloc, 2);
        if (sub == 0) {
            float alpha = __expf(mold - mnew);
            Arow[rr] = alpha;
            Mrow[rr] = mnew;
            Lrow[rr] = Lrow[rr] * alpha + sloc;
        }
        __syncthreads();

        // rescale O and O += P @ V
        float al[4];
        #pragma unroll
        for (int i = 0; i < 4; i++) al[i] = Arow[r0 + i];
        #pragma unroll
        for (int i = 0; i < 4; i++)
            #pragma unroll
            for (int j = 0; j < 4; j++) accO[i][j] *= al[i];

        #pragma unroll 4
        for (int k = 0; k < 64; k++) {
            float pv[4], vv[4];
            #pragma unroll
            for (int i = 0; i < 4; i++) pv[i] = Ss[(r0 + i) * ALD + k];
            #pragma unroll
            for (int j = 0; j < 4; j++) vv[j] = Vs[k * ALD + c0 + j];
            #pragma unroll
            for (int i = 0; i < 4; i++)
                #pragma unroll
                for (int j = 0; j < 4; j++)
                    accO[i][j] = fmaf(pv[i], vv[j], accO[i][j]);
        }
    }

    float linv[4];
    #pragma unroll
    for (int i = 0; i < 4; i++) linv[i] = 1.f / Lrow[r0 + i];
    #pragma unroll
    for (int i = 0; i < 4; i++)
        #pragma unroll
        for (int j = 0; j < 4; j++)
            o[(size_t)(b * TT + qt * 64 + r0 + i) * DD + h * DHH + c0 + j] =
                accO[i][j] * linv[i];
}

// ---------------- launcher ---------------------------------------------------
extern "C" void kernel_launch(void* const* d_in, const int* in_sizes, int n_in,
                              void* d_out, int out_size)
{
    const int*   ids  = (const int*)  d_in[0];
    const float* tok  = (const float*)d_in[1];
    const float* pos  = (const float*)d_in[2];
    const float* ln1s = (const float*)d_in[3];
    const float* ln1b = (const float*)d_in[4];
    const float* Wqkv = (const float*)d_in[5];
    const float* Wout = (const float*)d_in[6];
    const float* ln2s = (const float*)d_in[7];
    const float* ln2b = (const float*)d_in[8];
    const float* W1   = (const float*)d_in[9];
    const float* W2   = (const float*)d_in[10];
    const float* lnfs = (const float*)d_in[11];
    const float* lnfb = (const float*)d_in[12];
    float* out = (float*)d_out;

    float *x, *h, *qkv, *o, *a;
    cudaGetSymbolAddress((void**)&x,   g_x);
    cudaGetSymbolAddress((void**)&h,   g_h);
    cudaGetSymbolAddress((void**)&qkv, g_qkv);
    cudaGetSymbolAddress((void**)&o,   g_o);
    cudaGetSymbolAddress((void**)&a,   g_a);

    cudaFuncSetAttribute(attn_kernel,
                         cudaFuncAttributeMaxDynamicSharedMemorySize, ATTN_SMEM);

    embed_kernel<<<(MROWS * DD + 255) / 256, 256>>>(ids, tok, pos, x);

    for (int l = 0; l < LL; l++) {
        ln_kernel<<<MROWS, 256>>>(x, ln1s + (size_t)l * DD, ln1b + (size_t)l * DD, h);
        gemm128<0><<<dim3(3 * DD / 128, MROWS / 128), 256>>>(
            h, Wqkv + (size_t)l * DD * 3 * DD, nullptr, qkv, MROWS, 3 * DD, DD);
        attn_kernel<<<dim3(TT / 64, BB * HH), 256, ATTN_SMEM>>>(qkv, o);
        gemm128<1><<<dim3(DD / 128, MROWS / 128), 256>>>(
            o, Wout + (size_t)l * DD * DD, x, x, MROWS, DD, DD);
        ln_kernel<<<MROWS, 256>>>(x, ln2s + (size_t)l * DD, ln2b + (size_t)l * DD, h);
        gemm128<2><<<dim3(DFFF / 128, MROWS / 128), 256>>>(
            h, W1 + (size_t)l * DD * DFFF, nullptr, a, MROWS, DFFF, DD);
        gemm128<1><<<dim3(DD / 128, MROWS / 128), 256>>>(
            a, W2 + (size_t)l * DFFF * DD, x, x, MROWS, DD, DFFF);
    }

    ln_kernel<<<MROWS, 256>>>(x, lnfs, lnfb, out);
}

// round 4
// speedup vs baseline: 2.0189x; 2.0189x over previous
#include <cuda_runtime.h>
#include <cuda_bf16.h>
#include <math.h>
#include <stdint.h>

// Problem constants
#define BB 2
#define TT 1024
#define DD 1024
#define HH 16
#define LL 6
#define DHH 64
#define DFFF 2048
#define MROWS (BB*TT)   // 2048
#define D3 (3*DD)

// ---------------- scratch (device globals: no allocation allowed) ----------
__device__ float g_x  [MROWS * DD];     // residual stream (fp32)
__device__ float g_qkv[MROWS * D3];     // qkv (fp32, for attention)
__device__ __nv_bfloat16 g_h_hi[MROWS*DD],   g_h_lo[MROWS*DD];    // LN out
__device__ __nv_bfloat16 g_o_hi[MROWS*DD],   g_o_lo[MROWS*DD];    // attn out
__device__ __nv_bfloat16 g_a_hi[MROWS*DFFF], g_a_lo[MROWS*DFFF];  // gelu out
// transposed [N,K] bf16 hi/lo weights
__device__ __nv_bfloat16 g_WqkvT_hi[LL*D3*DD],   g_WqkvT_lo[LL*D3*DD];
__device__ __nv_bfloat16 g_WoutT_hi[LL*DD*DD],   g_WoutT_lo[LL*DD*DD];
__device__ __nv_bfloat16 g_W1T_hi [LL*DFFF*DD],  g_W1T_lo [LL*DFFF*DD];
__device__ __nv_bfloat16 g_W2T_hi [LL*DD*DFFF],  g_W2T_lo [LL*DD*DFFF];

// ================= helpers =================
__device__ __forceinline__ uint32_t smem_u32(const void* p){
    uint32_t a;
    asm("{ .reg .u64 t; cvta.to.shared.u64 t, %1; cvt.u32.u64 %0, t; }"
        : "=r"(a) : "l"(p));
    return a;
}

__device__ __forceinline__ void ldsm_x4(uint32_t a, uint32_t& r0, uint32_t& r1,
                                        uint32_t& r2, uint32_t& r3){
    asm volatile("ldmatrix.sync.aligned.m8n8.x4.shared.b16 {%0,%1,%2,%3}, [%4];"
                 : "=r"(r0), "=r"(r1), "=r"(r2), "=r"(r3) : "r"(a));
}
__device__ __forceinline__ void ldsm_x2(uint32_t a, uint32_t& r0, uint32_t& r1){
    asm volatile("ldmatrix.sync.aligned.m8n8.x2.shared.b16 {%0,%1}, [%2];"
                 : "=r"(r0), "=r"(r1) : "r"(a));
}
__device__ __forceinline__ void mma_bf16(float* c, const uint32_t* a,
                                         const uint32_t* b){
    asm volatile(
        "mma.sync.aligned.m16n8k16.row.col.f32.bf16.bf16.f32 "
        "{%0,%1,%2,%3}, {%4,%5,%6,%7}, {%8,%9}, {%0,%1,%2,%3};"
        : "+f"(c[0]), "+f"(c[1]), "+f"(c[2]), "+f"(c[3])
        : "r"(a[0]), "r"(a[1]), "r"(a[2]), "r"(a[3]), "r"(b[0]), "r"(b[1]));
}
__device__ __forceinline__ void cp16(uint32_t dst, const void* src){
    asm volatile("cp.async.cg.shared.global [%0], [%1], 16;"
                 :: "r"(dst), "l"(src));
}
#define CP_COMMIT() asm volatile("cp.async.commit_group;" ::: "memory")
#define CP_WAIT1()  asm volatile("cp.async.wait_group 1;" ::: "memory")
#define CP_WAIT0()  asm volatile("cp.async.wait_group 0;" ::: "memory")

// ---------------- embedding -------------------------------------------------
__global__ void embed_kernel(const int* __restrict__ ids,
                             const float* __restrict__ tok,
                             const float* __restrict__ pos,
                             float* __restrict__ x)
{
    int idx = blockIdx.x * blockDim.x + threadIdx.x;
    if (idx >= MROWS * DD) return;
    int d  = idx & (DD - 1);
    int bt = idx / DD;
    int t  = bt & (TT - 1);
    x[idx] = tok[(size_t)ids[bt] * DD + d] + pos[t * DD + d];
}

// ---------------- weight transpose + bf16 hi/lo split -----------------------
__global__ void twk(const float* __restrict__ W,
                    __nv_bfloat16* __restrict__ hi,
                    __nv_bfloat16* __restrict__ lo, int K, int N)
{
    __shared__ float t[32][33];
    int n0 = blockIdx.x * 32, k0 = blockIdx.y * 32;
    int tx = threadIdx.x, ty = threadIdx.y;   // 32 x 8
    #pragma unroll
    for (int i = 0; i < 32; i += 8)
        t[ty + i][tx] = W[(size_t)(k0 + ty + i) * N + n0 + tx];
    __syncthreads();
    #pragma unroll
    for (int i = 0; i < 32; i += 8) {
        float v = t[tx][ty + i];
        __nv_bfloat16 h = __float2bfloat16(v);
        size_t o = (size_t)(n0 + ty + i) * K + k0 + tx;
        hi[o] = h;
        lo[o] = __float2bfloat16(v - __bfloat162float(h));
    }
}

// ---------------- layernorm (biased var, eps 1e-5) --------------------------
template<bool BF>
__global__ void ln_kernel(const float* __restrict__ x,
                          const float* __restrict__ s,
                          const float* __restrict__ b,
                          float* __restrict__ y,
                          __nv_bfloat16* __restrict__ yhi,
                          __nv_bfloat16* __restrict__ ylo)
{
    int row = blockIdx.x;
    const float* xr = x + (size_t)row * DD;

    float sum = 0.f, sq = 0.f;
    int c4 = threadIdx.x;
    float4 v = ((const float4*)xr)[c4];
    sum = v.x + v.y + v.z + v.w;
    sq  = v.x*v.x + v.y*v.y + v.z*v.z + v.w*v.w;

    __shared__ float rs[8], rq[8];
    for (int o = 16; o > 0; o >>= 1) {
        sum += __shfl_xor_sync(0xffffffffu, sum, o);
        sq  += __shfl_xor_sync(0xffffffffu, sq,  o);
    }
    int wid = threadIdx.x >> 5;
    if ((threadIdx.x & 31) == 0) { rs[wid] = sum; rq[wid] = sq; }
    __syncthreads();
    if (threadIdx.x < 8) { sum = rs[threadIdx.x]; sq = rq[threadIdx.x]; }
    else                 { sum = 0.f; sq = 0.f; }
    if (threadIdx.x < 32) {
        for (int o = 4; o > 0; o >>= 1) {
            sum += __shfl_xor_sync(0xffffffffu, sum, o);
            sq  += __shfl_xor_sync(0xffffffffu, sq,  o);
        }
    }
    __shared__ float s_mean, s_inv;
    if (threadIdx.x == 0) {
        float mean = sum * (1.f / DD);
        float var  = sq * (1.f / DD) - mean * mean;
        s_mean = mean;
        s_inv  = rsqrtf(var + 1e-5f);
    }
    __syncthreads();
    float mean = s_mean, inv = s_inv;

    float4 sv = ((const float4*)s)[c4];
    float4 bv = ((const float4*)b)[c4];
    float ov[4];
    ov[0] = (v.x - mean) * inv * sv.x + bv.x;
    ov[1] = (v.y - mean) * inv * sv.y + bv.y;
    ov[2] = (v.z - mean) * inv * sv.z + bv.z;
    ov[3] = (v.w - mean) * inv * sv.w + bv.w;
    if (BF) {
        size_t base = (size_t)row * DD + c4 * 4;
        #pragma unroll
        for (int j = 0; j < 4; j++) {
            __nv_bfloat16 h = __float2bfloat16(ov[j]);
            yhi[base + j] = h;
            ylo[base + j] = __float2bfloat16(ov[j] - __bfloat162float(h));
        }
    } else {
        float4 o4 = make_float4(ov[0], ov[1], ov[2], ov[3]);
        ((float4*)(y + (size_t)row * DD))[c4] = o4;
    }
}

// ================= mma.sync bf16 GEMM ========================================
// C[M,N] = epi( A @ B^T ), A=[M,K] hi/lo bf16, B=[N,K] hi/lo bf16
// EPI: 0 = store fp32, 1 = X + acc, 2 = GELU -> bf16 hi/lo
// smem tile: 128 rows x 32 bf16 cols, row pitch 80 B (conflict-free ldmatrix)
#define TPITCH 80
#define TILE_B (128 * TPITCH)        // 10240 per tile
#define STAGE_B (4 * TILE_B)         // 40960 per stage (Ahi,Alo,Bhi,Blo)
#define GSM_TOTAL (2 * STAGE_B)      // 81920

__device__ __forceinline__ void fill_cp(uint32_t dst, const __nv_bfloat16* g,
                                        int K, int tid)
{
    // 128 rows x 64B, as 512 16B chunks, 256 threads -> 2 each
    #pragma unroll
    for (int i = 0; i < 2; i++) {
        int ch = tid + (i << 8);
        int r = ch >> 2, c = ch & 3;
        cp16(dst + r * TPITCH + c * 16,
             (const char*)g + (size_t)r * K * 2 + c * 16);
    }
}

template<int EPI>
__global__ __launch_bounds__(256, 1) void gemm_mma(
    const __nv_bfloat16* __restrict__ Ahi, const __nv_bfloat16* __restrict__ Alo,
    const __nv_bfloat16* __restrict__ Bhi, const __nv_bfloat16* __restrict__ Blo,
    const float* __restrict__ X, float* __restrict__ C,
    __nv_bfloat16* __restrict__ Chi, __nv_bfloat16* __restrict__ Clo,
    int M, int N, int K)
{
    extern __shared__ char sm[];
    uint32_t sb = smem_u32(sm);
    int tid  = threadIdx.x;
    int lane = tid & 31, w = tid >> 5;
    int wm = (w >> 2) * 64, wn = (w & 3) * 32;
    int m0 = blockIdx.y * 128, n0 = blockIdx.x * 128;

    const __nv_bfloat16* pAhi = Ahi + (size_t)m0 * K;
    const __nv_bfloat16* pAlo = Alo + (size_t)m0 * K;
    const __nv_bfloat16* pBhi = Bhi + (size_t)n0 * K;
    const __nv_bfloat16* pBlo = Blo + (size_t)n0 * K;

    float acc[4][4][4] = {};
    int S = K >> 5;

    // prologue: stage 0
    fill_cp(sb,              pAhi, K, tid);
    fill_cp(sb + TILE_B,     pAlo, K, tid);
    fill_cp(sb + 2 * TILE_B, pBhi, K, tid);
    fill_cp(sb + 3 * TILE_B, pBlo, K, tid);
    CP_COMMIT();

    // ldmatrix lane addressing (within-tile offsets)
    int aRow = wm + (lane & 15);            // + mt*16
    int aCol = (lane >> 4);                 // + k16*2
    int bRow = wn + (lane & 7);             // + nt*8
    int bCol = ((lane >> 3) & 1);           // + k16*2

    for (int s = 0; s < S; s++) {
        uint32_t buf = sb + (s & 1) * STAGE_B;
        if (s + 1 < S) {
            uint32_t nbuf = sb + ((s + 1) & 1) * STAGE_B;
            int k0 = (s + 1) << 5;
            fill_cp(nbuf,              pAhi + k0, K, tid);
            fill_cp(nbuf + TILE_B,     pAlo + k0, K, tid);
            fill_cp(nbuf + 2 * TILE_B, pBhi + k0, K, tid);
            fill_cp(nbuf + 3 * TILE_B, pBlo + k0, K, tid);
            CP_COMMIT();
            CP_WAIT1();
        } else {
            CP_WAIT0();
        }
        __syncthreads();

        #pragma unroll
        for (int k16 = 0; k16 < 2; k16++) {
            uint32_t ah[4][4], al[4][4];
            #pragma unroll
            for (int mt = 0; mt < 4; mt++) {
                uint32_t off = (uint32_t)(aRow + mt * 16) * TPITCH +
                               (uint32_t)(aCol + k16 * 2) * 16;
                ldsm_x4(buf + off, ah[mt][0], ah[mt][1], ah[mt][2], ah[mt][3]);
                ldsm_x4(buf + TILE_B + off, al[mt][0], al[mt][1], al[mt][2], al[mt][3]);
            }
            uint32_t bh[4][2], bl[4][2];
            #pragma unroll
            for (int nt = 0; nt < 4; nt++) {
                uint32_t off = (uint32_t)(bRow + nt * 8) * TPITCH +
                               (uint32_t)(bCol + k16 * 2) * 16;
                ldsm_x2(buf + 2 * TILE_B + off, bh[nt][0], bh[nt][1]);
                ldsm_x2(buf + 3 * TILE_B + off, bl[nt][0], bl[nt][1]);
            }
            #pragma unroll
            for (int mt = 0; mt < 4; mt++)
                #pragma unroll
                for (int nt = 0; nt < 4; nt++) {
                    mma_bf16(acc[mt][nt], ah[mt], bh[nt]);
                    mma_bf16(acc[mt][nt], al[mt], bh[nt]);
                    mma_bf16(acc[mt][nt], ah[mt], bl[nt]);
                }
        }
        __syncthreads();
    }

    // epilogue: frag -> global
    #pragma unroll
    for (int mt = 0; mt < 4; mt++) {
        #pragma unroll
        for (int nt = 0; nt < 4; nt++) {
            float* cc = acc[mt][nt];
            int gr = m0 + wm + mt * 16 + (lane >> 2);
            int gc = n0 + wn + nt * 8 + (lane & 3) * 2;
            #pragma unroll
            for (int half = 0; half < 2; half++) {
                size_t base = (size_t)(gr + half * 8) * N + gc;
                float v0 = cc[half * 2], v1 = cc[half * 2 + 1];
                if (EPI == 0) {
                    C[base] = v0; C[base + 1] = v1;
                } else if (EPI == 1) {
                    C[base]     = v0 + X[base];
                    C[base + 1] = v1 + X[base + 1];
                } else {
                    float g0 = 0.5f * v0 * (1.f + erff(v0 * 0.70710678118654752f));
                    float g1 = 0.5f * v1 * (1.f + erff(v1 * 0.70710678118654752f));
                    __nv_bfloat16 h0 = __float2bfloat16(g0);
                    __nv_bfloat16 h1 = __float2bfloat16(g1);
                    Chi[base]     = h0;
                    Chi[base + 1] = h1;
                    Clo[base]     = __float2bfloat16(g0 - __bfloat162float(h0));
                    Clo[base + 1] = __float2bfloat16(g1 - __bfloat162float(h1));
                }
            }
        }
    }
}

// ---------------- flash attention (causal, DH=64, 64-row tiles) -------------
#define ALD 65
#define ATTN_SMEM ((4 * 64 * ALD + 3 * 64) * (int)sizeof(float))

__global__ __launch_bounds__(256) void attn_kernel(const float* __restrict__ qkv,
                                                   __nv_bfloat16* __restrict__ o_hi,
                                                   __nv_bfloat16* __restrict__ o_lo)
{
    extern __shared__ float smn[];
    float* Qs   = smn;
    float* Ks   = Qs + 64 * ALD;
    float* Vs   = Ks + 64 * ALD;
    float* Ss   = Vs + 64 * ALD;
    float* Mrow = Ss + 64 * ALD;
    float* Lrow = Mrow + 64;
    float* Arow = Lrow + 64;

    int qt = blockIdx.x;
    int bh = blockIdx.y;
    int b = bh / HH, h = bh % HH;
    int tid = threadIdx.x;
    int ty = tid >> 4, tx = tid & 15;
    int r0 = ty * 4, c0 = tx * 4;

    for (int e = tid; e < 64 * 64; e += 256) {
        int r = e >> 6, c = e & 63;
        Qs[r * ALD + c] = qkv[(size_t)(b * TT + qt * 64 + r) * D3 + h * DHH + c];
    }
    if (tid < 64) { Mrow[tid] = -1e30f; Lrow[tid] = 0.f; }

    float accO[4][4] = {};
    const float scale = 0.125f;

    for (int jt = 0; jt <= qt; jt++) {
        __syncthreads();
        for (int e = tid; e < 64 * 64; e += 256) {
            int r = e >> 6, c = e & 63;
            size_t rowoff = (size_t)(b * TT + jt * 64 + r) * D3;
            Ks[r * ALD + c] = qkv[rowoff + DD     + h * DHH + c];
            Vs[r * ALD + c] = qkv[rowoff + 2 * DD + h * DHH + c];
        }
        __syncthreads();

        float s[4][4] = {};
        #pragma unroll 4
        for (int k = 0; k < 64; k++) {
            float qv[4], kv[4];
            #pragma unroll
            for (int i = 0; i < 4; i++) qv[i] = Qs[(r0 + i) * ALD + k];
            #pragma unroll
            for (int j = 0; j < 4; j++) kv[j] = Ks[(c0 + j) * ALD + k];
            #pragma unroll
            for (int i = 0; i < 4; i++)
                #pragma unroll
                for (int j = 0; j < 4; j++)
                    s[i][j] = fmaf(qv[i], kv[j], s[i][j]);
        }
        bool diag = (jt == qt);
        #pragma unroll
        for (int i = 0; i < 4; i++)
            #pragma unroll
            for (int j = 0; j < 4; j++) {
                float v = s[i][j] * scale;
                if (diag && (c0 + j) > (r0 + i)) v = -1e30f;
                Ss[(r0 + i) * ALD + c0 + j] = v;
            }
        __syncthreads();

        int rr = tid >> 2, sub = tid & 3;
        float mloc = -1e30f;
        for (int c = sub * 16; c < sub * 16 + 16; c++)
            mloc = fmaxf(mloc, Ss[rr * ALD + c]);
        mloc = fmaxf(mloc, __shfl_xor_sync(0xffffffffu, mloc, 1));
        mloc = fmaxf(mloc, __shfl_xor_sync(0xffffffffu, mloc, 2));
        float mold = Mrow[rr];
        float mnew = fmaxf(mold, mloc);
        float sloc = 0.f;
        for (int c = sub * 16; c < sub * 16 + 16; c++) {
            float p = __expf(Ss[rr * ALD + c] - mnew);
            Ss[rr * ALD + c] = p;
            sloc += p;
        }
        sloc += __shfl_xor_sync(0xffffffffu, sloc, 1);
        sloc += __shfl_xor_sync(0xffffffffu, sloc, 2);
        if (sub == 0) {
            float alpha = __expf(mold - mnew);
            Arow[rr] = alpha;
            Mrow[rr] = mnew;
            Lrow[rr] = Lrow[rr] * alpha + sloc;
        }
        __syncthreads();

        float al[4];
        #pragma unroll
        for (int i = 0; i < 4; i++) al[i] = Arow[r0 + i];
        #pragma unroll
        for (int i = 0; i < 4; i++)
            #pragma unroll
            for (int j = 0; j < 4; j++) accO[i][j] *= al[i];

        #pragma unroll 4
        for (int k = 0; k < 64; k++) {
            float pv[4], vv[4];
            #pragma unroll
            for (int i = 0; i < 4; i++) pv[i] = Ss[(r0 + i) * ALD + k];
            #pragma unroll
            for (int j = 0; j < 4; j++) vv[j] = Vs[k * ALD + c0 + j];
            #pragma unroll
            for (int i = 0; i < 4; i++)
                #pragma unroll
                for (int j = 0; j < 4; j++)
                    accO[i][j] = fmaf(pv[i], vv[j], accO[i][j]);
        }
    }

    float linv[4];
    #pragma unroll
    for (int i = 0; i < 4; i++) linv[i] = 1.f / Lrow[r0 + i];
    #pragma unroll
    for (int i = 0; i < 4; i++)
        #pragma unroll
        for (int j = 0; j < 4; j++) {
            float val = accO[i][j] * linv[i];
            size_t ad = (size_t)(b * TT + qt * 64 + r0 + i) * DD + h * DHH + c0 + j;
            __nv_bfloat16 hv = __float2bfloat16(val);
            o_hi[ad] = hv;
            o_lo[ad] = __float2bfloat16(val - __bfloat162float(hv));
        }
}

// ---------------- launcher ---------------------------------------------------
extern "C" void kernel_launch(void* const* d_in, const int* in_sizes, int n_in,
                              void* d_out, int out_size)
{
    const int*   ids  = (const int*)  d_in[0];
    const float* tok  = (const float*)d_in[1];
    const float* pos  = (const float*)d_in[2];
    const float* ln1s = (const float*)d_in[3];
    const float* ln1b = (const float*)d_in[4];
    const float* Wqkv = (const float*)d_in[5];
    const float* Wout = (const float*)d_in[6];
    const float* ln2s = (const float*)d_in[7];
    const float* ln2b = (const float*)d_in[8];
    const float* W1   = (const float*)d_in[9];
    const float* W2   = (const float*)d_in[10];
    const float* lnfs = (const float*)d_in[11];
    const float* lnfb = (const float*)d_in[12];
    float* out = (float*)d_out;

    float *x, *qkv;
    __nv_bfloat16 *h_hi, *h_lo, *o_hi, *o_lo, *a_hi, *a_lo;
    __nv_bfloat16 *wqT_hi, *wqT_lo, *woT_hi, *woT_lo, *w1T_hi, *w1T_lo, *w2T_hi, *w2T_lo;
    cudaGetSymbolAddress((void**)&x,    g_x);
    cudaGetSymbolAddress((void**)&qkv,  g_qkv);
    cudaGetSymbolAddress((void**)&h_hi, g_h_hi);
    cudaGetSymbolAddress((void**)&h_lo, g_h_lo);
    cudaGetSymbolAddress((void**)&o_hi, g_o_hi);
    cudaGetSymbolAddress((void**)&o_lo, g_o_lo);
    cudaGetSymbolAddress((void**)&a_hi, g_a_hi);
    cudaGetSymbolAddress((void**)&a_lo, g_a_lo);
    cudaGetSymbolAddress((void**)&wqT_hi, g_WqkvT_hi);
    cudaGetSymbolAddress((void**)&wqT_lo, g_WqkvT_lo);
    cudaGetSymbolAddress((void**)&woT_hi, g_WoutT_hi);
    cudaGetSymbolAddress((void**)&woT_lo, g_WoutT_lo);
    cudaGetSymbolAddress((void**)&w1T_hi, g_W1T_hi);
    cudaGetSymbolAddress((void**)&w1T_lo, g_W1T_lo);
    cudaGetSymbolAddress((void**)&w2T_hi, g_W2T_hi);
    cudaGetSymbolAddress((void**)&w2T_lo, g_W2T_lo);

    cudaFuncSetAttribute(attn_kernel,
                         cudaFuncAttributeMaxDynamicSharedMemorySize, ATTN_SMEM);
    cudaFuncSetAttribute(gemm_mma<0>,
                         cudaFuncAttributeMaxDynamicSharedMemorySize, GSM_TOTAL);
    cudaFuncSetAttribute(gemm_mma<1>,
                         cudaFuncAttributeMaxDynamicSharedMemorySize, GSM_TOTAL);
    cudaFuncSetAttribute(gemm_mma<2>,
                         cudaFuncAttributeMaxDynamicSharedMemorySize, GSM_TOTAL);

    // weight transpose + bf16 split (all layers)
    dim3 tb(32, 8);
    for (int l = 0; l < LL; l++) {
        twk<<<dim3(D3 / 32, DD / 32), tb>>>(
            Wqkv + (size_t)l * DD * D3,
            wqT_hi + (size_t)l * D3 * DD, wqT_lo + (size_t)l * D3 * DD, DD, D3);
        twk<<<dim3(DD / 32, DD / 32), tb>>>(
            Wout + (size_t)l * DD * DD,
            woT_hi + (size_t)l * DD * DD, woT_lo + (size_t)l * DD * DD, DD, DD);
        twk<<<dim3(DFFF / 32, DD / 32), tb>>>(
            W1 + (size_t)l * DD * DFFF,
            w1T_hi + (size_t)l * DFFF * DD, w1T_lo + (size_t)l * DFFF * DD, DD, DFFF);
        twk<<<dim3(DD / 32, DFFF / 32), tb>>>(
            W2 + (size_t)l * DFFF * DD,
            w2T_hi + (size_t)l * DD * DFFF, w2T_lo + (size_t)l * DD * DFFF, DFFF, DD);
    }

    embed_kernel<<<(MROWS * DD + 255) / 256, 256>>>(ids, tok, pos, x);

    for (int l = 0; l < LL; l++) {
        ln_kernel<true><<<MROWS, 256>>>(x, ln1s + (size_t)l * DD, ln1b + (size_t)l * DD,
                                        nullptr, h_hi, h_lo);
        gemm_mma<0><<<dim3(D3 / 128, MROWS / 128), 256, GSM_TOTAL>>>(
            h_hi, h_lo,
            wqT_hi + (size_t)l * D3 * DD, wqT_lo + (size_t)l * D3 * DD,
            nullptr, qkv, nullptr, nullptr, MROWS, D3, DD);
        attn_kernel<<<dim3(TT / 64, BB * HH), 256, ATTN_SMEM>>>(qkv, o_hi, o_lo);
        gemm_mma<1><<<dim3(DD / 128, MROWS / 128), 256, GSM_TOTAL>>>(
            o_hi, o_lo,
            woT_hi + (size_t)l * DD * DD, woT_lo + (size_t)l * DD * DD,
            x, x, nullptr, nullptr, MROWS, DD, DD);
        ln_kernel<true><<<MROWS, 256>>>(x, ln2s + (size_t)l * DD, ln2b + (size_t)l * DD,
                                        nullptr, h_hi, h_lo);
        gemm_mma<2><<<dim3(DFFF / 128, MROWS / 128), 256, GSM_TOTAL>>>(
            h_hi, h_lo,
            w1T_hi + (size_t)l * DFFF * DD, w1T_lo + (size_t)l * DFFF * DD,
            nullptr, nullptr, a_hi, a_lo, MROWS, DFFF, DD);
        gemm_mma<1><<<dim3(DD / 128, MROWS / 128), 256, GSM_TOTAL>>>(
            a_hi, a_lo,
            w2T_hi + (size_t)l * DD * DFFF, w2T_lo + (size_t)l * DD * DFFF,
            x, x, nullptr, nullptr, MROWS, DD, DFFF);
    }

    ln_kernel<false><<<MROWS, 256>>>(x, lnfs, lnfb, out, nullptr, nullptr);
}

// round 6
// speedup vs baseline: 2.6943x; 1.3345x over previous
#include <cuda_runtime.h>
#include <cuda_bf16.h>
#include <math.h>
#include <stdint.h>

// Problem constants
#define BB 2
#define TT 1024
#define DD 1024
#define HH 16
#define LL 6
#define DHH 64
#define DFFF 2048
#define MROWS (BB*TT)   // 2048
#define D3 (3*DD)

// ---------------- scratch (device globals) ----------------------------------
__device__ float g_x[MROWS * DD];                                   // residual
__device__ __nv_bfloat16 g_h_hi[MROWS*DD],    g_h_lo[MROWS*DD];     // LN out
__device__ __nv_bfloat16 g_qkv_hi[MROWS*D3],  g_qkv_lo[MROWS*D3];   // qkv
__device__ __nv_bfloat16 g_o_hi[MROWS*DD],    g_o_lo[MROWS*DD];     // attn out
__device__ __nv_bfloat16 g_a_hi[MROWS*DFFF],  g_a_lo[MROWS*DFFF];   // gelu out
__device__ __nv_bfloat16 g_WqkvT_hi[LL*D3*DD],   g_WqkvT_lo[LL*D3*DD];
__device__ __nv_bfloat16 g_WoutT_hi[LL*DD*DD],   g_WoutT_lo[LL*DD*DD];
__device__ __nv_bfloat16 g_W1T_hi [LL*DFFF*DD],  g_W1T_lo [LL*DFFF*DD];
__device__ __nv_bfloat16 g_W2T_hi [LL*DD*DFFF],  g_W2T_lo [LL*DD*DFFF];

// ================= helpers =================
__device__ __forceinline__ uint32_t smem_u32(const void* p){
    uint32_t a;
    asm("{ .reg .u64 t; cvta.to.shared.u64 t, %1; cvt.u32.u64 %0, t; }"
        : "=r"(a) : "l"(p));
    return a;
}
__device__ __forceinline__ void ldsm_x4(uint32_t a, uint32_t& r0, uint32_t& r1,
                                        uint32_t& r2, uint32_t& r3){
    asm volatile("ldmatrix.sync.aligned.m8n8.x4.shared.b16 {%0,%1,%2,%3}, [%4];"
                 : "=r"(r0), "=r"(r1), "=r"(r2), "=r"(r3) : "r"(a));
}
__device__ __forceinline__ void ldsm_x2(uint32_t a, uint32_t& r0, uint32_t& r1){
    asm volatile("ldmatrix.sync.aligned.m8n8.x2.shared.b16 {%0,%1}, [%2];"
                 : "=r"(r0), "=r"(r1) : "r"(a));
}
__device__ __forceinline__ void ldsm_x2t(uint32_t a, uint32_t& r0, uint32_t& r1){
    asm volatile("ldmatrix.sync.aligned.m8n8.x2.trans.shared.b16 {%0,%1}, [%2];"
                 : "=r"(r0), "=r"(r1) : "r"(a));
}
__device__ __forceinline__ void mma_bf16(float* c, const uint32_t* a,
                                         const uint32_t* b){
    asm volatile(
        "mma.sync.aligned.m16n8k16.row.col.f32.bf16.bf16.f32 "
        "{%0,%1,%2,%3}, {%4,%5,%6,%7}, {%8,%9}, {%0,%1,%2,%3};"
        : "+f"(c[0]), "+f"(c[1]), "+f"(c[2]), "+f"(c[3])
        : "r"(a[0]), "r"(a[1]), "r"(a[2]), "r"(a[3]), "r"(b[0]), "r"(b[1]));
}
__device__ __forceinline__ void cp16(uint32_t dst, const void* src){
    asm volatile("cp.async.cg.shared.global [%0], [%1], 16;"
                 :: "r"(dst), "l"(src));
}
#define CP_COMMIT() asm volatile("cp.async.commit_group;" ::: "memory")
#define CP_WAIT1()  asm volatile("cp.async.wait_group 1;" ::: "memory")
#define CP_WAIT0()  asm volatile("cp.async.wait_group 0;" ::: "memory")

__device__ __forceinline__ uint32_t pack_bf2(float lo_val, float hi_val){
    __nv_bfloat162 t = __floats2bfloat162_rn(lo_val, hi_val);
    return *(uint32_t*)&t;
}
__device__ __forceinline__ void split_bf(float v, float& hi_f, float& lo_f){
    __nv_bfloat16 h = __float2bfloat16(v);
    hi_f = __bfloat162float(h);
    lo_f = v - hi_f;
}

// ---------------- embedding -------------------------------------------------
__global__ void embed_kernel(const int* __restrict__ ids,
                             const float* __restrict__ tok,
                             const float* __restrict__ pos,
                             float* __restrict__ x)
{
    int idx = blockIdx.x * blockDim.x + threadIdx.x;
    if (idx >= MROWS * DD) return;
    int d  = idx & (DD - 1);
    int bt = idx / DD;
    int t  = bt & (TT - 1);
    x[idx] = tok[(size_t)ids[bt] * DD + d] + pos[t * DD + d];
}

// ---------------- weight transpose + bf16 hi/lo split -----------------------
__global__ void twk(const float* __restrict__ W,
                    __nv_bfloat16* __restrict__ hi,
                    __nv_bfloat16* __restrict__ lo, int K, int N)
{
    __shared__ float t[32][33];
    int n0 = blockIdx.x * 32, k0 = blockIdx.y * 32;
    int tx = threadIdx.x, ty = threadIdx.y;   // 32 x 8
    #pragma unroll
    for (int i = 0; i < 32; i += 8)
        t[ty + i][tx] = W[(size_t)(k0 + ty + i) * N + n0 + tx];
    __syncthreads();
    #pragma unroll
    for (int i = 0; i < 32; i += 8) {
        float v = t[tx][ty + i];
        __nv_bfloat16 h = __float2bfloat16(v);
        size_t o = (size_t)(n0 + ty + i) * K + k0 + tx;
        hi[o] = h;
        lo[o] = __float2bfloat16(v - __bfloat162float(h));
    }
}

// ---------------- layernorm (biased var, eps 1e-5) --------------------------
template<bool BF>
__global__ void ln_kernel(const float* __restrict__ x,
                          const float* __restrict__ s,
                          const float* __restrict__ b,
                          float* __restrict__ y,
                          __nv_bfloat16* __restrict__ yhi,
                          __nv_bfloat16* __restrict__ ylo)
{
    int row = blockIdx.x;
    const float* xr = x + (size_t)row * DD;

    float sum = 0.f, sq = 0.f;
    int c4 = threadIdx.x;
    float4 v = ((const float4*)xr)[c4];
    sum = v.x + v.y + v.z + v.w;
    sq  = v.x*v.x + v.y*v.y + v.z*v.z + v.w*v.w;

    __shared__ float rs[8], rq[8];
    for (int o = 16; o > 0; o >>= 1) {
        sum += __shfl_xor_sync(0xffffffffu, sum, o);
        sq  += __shfl_xor_sync(0xffffffffu, sq,  o);
    }
    int wid = threadIdx.x >> 5;
    if ((threadIdx.x & 31) == 0) { rs[wid] = sum; rq[wid] = sq; }
    __syncthreads();
    if (threadIdx.x < 8) { sum = rs[threadIdx.x]; sq = rq[threadIdx.x]; }
    else                 { sum = 0.f; sq = 0.f; }
    if (threadIdx.x < 32) {
        for (int o = 4; o > 0; o >>= 1) {
            sum += __shfl_xor_sync(0xffffffffu, sum, o);
            sq  += __shfl_xor_sync(0xffffffffu, sq,  o);
        }
    }
    __shared__ float s_mean, s_inv;
    if (threadIdx.x == 0) {
        float mean = sum * (1.f / DD);
        float var  = sq * (1.f / DD) - mean * mean;
        s_mean = mean;
        s_inv  = rsqrtf(var + 1e-5f);
    }
    __syncthreads();
    float mean = s_mean, inv = s_inv;

    float4 sv = ((const float4*)s)[c4];
    float4 bv = ((const float4*)b)[c4];
    float ov[4];
    ov[0] = (v.x - mean) * inv * sv.x + bv.x;
    ov[1] = (v.y - mean) * inv * sv.y + bv.y;
    ov[2] = (v.z - mean) * inv * sv.z + bv.z;
    ov[3] = (v.w - mean) * inv * sv.w + bv.w;
    if (BF) {
        size_t base = (size_t)row * DD + c4 * 4;
        #pragma unroll
        for (int j = 0; j < 4; j += 2) {
            float h0, l0, h1, l1;
            split_bf(ov[j],     h0, l0);
            split_bf(ov[j + 1], h1, l1);
            *(uint32_t*)&yhi[base + j] = pack_bf2(h0, h1);
            *(uint32_t*)&ylo[base + j] = pack_bf2(l0, l1);
        }
    } else {
        float4 o4 = make_float4(ov[0], ov[1], ov[2], ov[3]);
        ((float4*)(y + (size_t)row * DD))[c4] = o4;
    }
}

// ================= mma.sync bf16 GEMM ========================================
// EPI: 1 = X + acc -> fp32, 2 = GELU -> bf16 hi/lo, 3 = bf16 hi/lo
#define TPITCH 80
#define TILE_B (128 * TPITCH)
#define STAGE_B (4 * TILE_B)
#define GSM_TOTAL (2 * STAGE_B)

__device__ __forceinline__ void fill_cp(uint32_t dst, const __nv_bfloat16* g,
                                        int K, int tid)
{
    #pragma unroll
    for (int i = 0; i < 2; i++) {
        int ch = tid + (i << 8);
        int r = ch >> 2, c = ch & 3;
        cp16(dst + r * TPITCH + c * 16,
             (const char*)g + (size_t)r * K * 2 + c * 16);
    }
}

template<int EPI>
__global__ __launch_bounds__(256, 1) void gemm_mma(
    const __nv_bfloat16* __restrict__ Ahi, const __nv_bfloat16* __restrict__ Alo,
    const __nv_bfloat16* __restrict__ Bhi, const __nv_bfloat16* __restrict__ Blo,
    const float* __restrict__ X, float* __restrict__ C,
    __nv_bfloat16* __restrict__ Chi, __nv_bfloat16* __restrict__ Clo,
    int M, int N, int K)
{
    extern __shared__ char sm[];
    uint32_t sb = smem_u32(sm);
    int tid  = threadIdx.x;
    int lane = tid & 31, w = tid >> 5;
    int wm = (w >> 2) * 64, wn = (w & 3) * 32;
    int m0 = blockIdx.y * 128, n0 = blockIdx.x * 128;

    const __nv_bfloat16* pAhi = Ahi + (size_t)m0 * K;
    const __nv_bfloat16* pAlo = Alo + (size_t)m0 * K;
    const __nv_bfloat16* pBhi = Bhi + (size_t)n0 * K;
    const __nv_bfloat16* pBlo = Blo + (size_t)n0 * K;

    float acc[4][4][4] = {};
    int S = K >> 5;

    fill_cp(sb,              pAhi, K, tid);
    fill_cp(sb + TILE_B,     pAlo, K, tid);
    fill_cp(sb + 2 * TILE_B, pBhi, K, tid);
    fill_cp(sb + 3 * TILE_B, pBlo, K, tid);
    CP_COMMIT();

    int aRow = wm + (lane & 15);
    int aCol = (lane >> 4);
    int bRow = wn + (lane & 7);
    int bCol = ((lane >> 3) & 1);

    for (int s = 0; s < S; s++) {
        uint32_t buf = sb + (s & 1) * STAGE_B;
        if (s + 1 < S) {
            uint32_t nbuf = sb + ((s + 1) & 1) * STAGE_B;
            int k0 = (s + 1) << 5;
            fill_cp(nbuf,              pAhi + k0, K, tid);
            fill_cp(nbuf + TILE_B,     pAlo + k0, K, tid);
            fill_cp(nbuf + 2 * TILE_B, pBhi + k0, K, tid);
            fill_cp(nbuf + 3 * TILE_B, pBlo + k0, K, tid);
            CP_COMMIT();
            CP_WAIT1();
        } else {
            CP_WAIT0();
        }
        __syncthreads();

        #pragma unroll
        for (int k16 = 0; k16 < 2; k16++) {
            uint32_t ah[4][4], al[4][4];
            #pragma unroll
            for (int mt = 0; mt < 4; mt++) {
                uint32_t off = (uint32_t)(aRow + mt * 16) * TPITCH +
                               (uint32_t)(aCol + k16 * 2) * 16;
                ldsm_x4(buf + off, ah[mt][0], ah[mt][1], ah[mt][2], ah[mt][3]);
                ldsm_x4(buf + TILE_B + off, al[mt][0], al[mt][1], al[mt][2], al[mt][3]);
            }
            uint32_t bh[4][2], bl[4][2];
            #pragma unroll
            for (int nt = 0; nt < 4; nt++) {
                uint32_t off = (uint32_t)(bRow + nt * 8) * TPITCH +
                               (uint32_t)(bCol + k16 * 2) * 16;
                ldsm_x2(buf + 2 * TILE_B + off, bh[nt][0], bh[nt][1]);
                ldsm_x2(buf + 3 * TILE_B + off, bl[nt][0], bl[nt][1]);
            }
            #pragma unroll
            for (int mt = 0; mt < 4; mt++)
                #pragma unroll
                for (int nt = 0; nt < 4; nt++) {
                    mma_bf16(acc[mt][nt], ah[mt], bh[nt]);
                    mma_bf16(acc[mt][nt], al[mt], bh[nt]);
                    mma_bf16(acc[mt][nt], ah[mt], bl[nt]);
                }
        }
        __syncthreads();
    }

    #pragma unroll
    for (int mt = 0; mt < 4; mt++) {
        #pragma unroll
        for (int nt = 0; nt < 4; nt++) {
            float* cc = acc[mt][nt];
            int gr = m0 + wm + mt * 16 + (lane >> 2);
            int gc = n0 + wn + nt * 8 + (lane & 3) * 2;
            #pragma unroll
            for (int half = 0; half < 2; half++) {
                size_t base = (size_t)(gr + half * 8) * N + gc;
                float v0 = cc[half * 2], v1 = cc[half * 2 + 1];
                if (EPI == 1) {
                    C[base]     = v0 + X[base];
                    C[base + 1] = v1 + X[base + 1];
                } else {
                    if (EPI == 2) {
                        v0 = 0.5f * v0 * (1.f + erff(v0 * 0.70710678118654752f));
                        v1 = 0.5f * v1 * (1.f + erff(v1 * 0.70710678118654752f));
                    }
                    float h0, l0, h1, l1;
                    split_bf(v0, h0, l0);
                    split_bf(v1, h1, l1);
                    *(uint32_t*)&Chi[base] = pack_bf2(h0, h1);
                    *(uint32_t*)&Clo[base] = pack_bf2(l0, l1);
                }
            }
        }
    }
}

// ================= tensor-core flash attention ==============================
// grid (16 qtiles, 32 bh), 128 threads; warp w owns q rows [w*16, w*16+16)
// Tile rows are DH=64 bf16 = 128 B; pitch 144 B (9*16 -> ldmatrix conflict-free)
#define APITCH 144
#define ATILE (64 * APITCH)            // 9216 B per 64x64 bf16 tile
#define ASTAGE (4 * ATILE)             // Khi,Klo,Vhi,Vlo
#define ATTN_SMEM (2 * ATILE + 2 * ASTAGE)  // Q hi/lo + 2 stages = 92160

__device__ __forceinline__ void attn_fill(uint32_t dst,
                                          const __nv_bfloat16* ghi,
                                          const __nv_bfloat16* glo, int tid)
{
    // 64 rows x 8 16B-chunks, hi then lo: 1024 chunks / 128 thr = 8 each
    #pragma unroll
    for (int i = 0; i < 8; i++) {
        int ch = tid + (i << 7);
        int r = (ch & 511) >> 3, c = ch & 7;
        const __nv_bfloat16* src = (ch < 512) ? ghi : glo;
        uint32_t d = dst + ((ch < 512) ? 0 : ATILE) + r * APITCH + c * 16;
        cp16(d, (const char*)src + (size_t)r * D3 * 2 + c * 16);
    }
}

__global__ __launch_bounds__(128) void attn_mma(
    const __nv_bfloat16* __restrict__ qkv_hi,
    const __nv_bfloat16* __restrict__ qkv_lo,
    __nv_bfloat16* __restrict__ o_hi,
    __nv_bfloat16* __restrict__ o_lo)
{
    extern __shared__ char sm[];
    uint32_t sb = smem_u32(sm);
    int qt = blockIdx.x, bh = blockIdx.y;
    int b = bh >> 4, h = bh & 15;
    int tid = threadIdx.x, lane = tid & 31, w = tid >> 5;

    size_t qrow = (size_t)(b * TT + qt * 64);
    const __nv_bfloat16* gq_hi = qkv_hi + qrow * D3 + h * DHH;
    const __nv_bfloat16* gq_lo = qkv_lo + qrow * D3 + h * DHH;

    uint32_t sQ = sb;                 // Q hi/lo
    uint32_t sS0 = sb + 2 * ATILE;    // stage 0: Khi, Klo, Vhi, Vlo

    // prologue: Q + stage 0 (K/V tile jt=0)
    attn_fill(sQ, gq_hi, gq_lo, tid);
    {
        const __nv_bfloat16* gk_hi = qkv_hi + (size_t)(b * TT) * D3 + DD + h * DHH;
        const __nv_bfloat16* gk_lo = qkv_lo + (size_t)(b * TT) * D3 + DD + h * DHH;
        attn_fill(sS0,             gk_hi, gk_lo, tid);
        attn_fill(sS0 + 2 * ATILE, gk_hi + DD, gk_lo + DD, tid);  // V = K + DD
    }
    CP_COMMIT();
    CP_WAIT0();
    __syncthreads();

    // Q fragments (4 k16 blocks), hi and lo
    uint32_t qh[4][4], ql[4][4];
    {
        uint32_t rowoff = (uint32_t)(w * 16 + (lane & 15)) * APITCH;
        uint32_t coloff = (uint32_t)(lane >> 4) * 16;
        #pragma unroll
        for (int kb = 0; kb < 4; kb++) {
            uint32_t off = rowoff + kb * 32 + coloff;
            ldsm_x4(sQ + off,         qh[kb][0], qh[kb][1], qh[kb][2], qh[kb][3]);
            ldsm_x4(sQ + ATILE + off, ql[kb][0], ql[kb][1], ql[kb][2], ql[kb][3]);
        }
    }

    float oacc[8][4] = {};
    float mrow[2] = {-1e30f, -1e30f};
    float lrow[2] = {0.f, 0.f};

    int r0loc = w * 16 + (lane >> 2);          // local q row (first)
    int r0g = qt * 64 + r0loc;                  // global q rows r0g, r0g+8
    int cql = (lane & 3) * 2;                   // col pair base within n8

    for (int jt = 0; jt <= qt; jt++) {
        uint32_t buf = sS0 + (jt & 1) * ASTAGE;
        // prefetch jt+1
        if (jt + 1 <= qt) {
            uint32_t nbuf = sS0 + ((jt + 1) & 1) * ASTAGE;
            size_t krow = (size_t)(b * TT + (jt + 1) * 64);
            const __nv_bfloat16* gk_hi = qkv_hi + krow * D3 + DD + h * DHH;
            const __nv_bfloat16* gk_lo = qkv_lo + krow * D3 + DD + h * DHH;
            attn_fill(nbuf,             gk_hi, gk_lo, tid);
            attn_fill(nbuf + 2 * ATILE, gk_hi + DD, gk_lo + DD, tid);
            CP_COMMIT();
        }

        // ---- S = Q K^T (3-term split) ----
        float s[8][4] = {};
        #pragma unroll
        for (int kb = 0; kb < 4; kb++) {
            uint32_t kcol = (uint32_t)(((lane >> 3) & 1) * 8 + kb * 16) * 2;
            #pragma unroll
            for (int nt = 0; nt < 8; nt++) {
                uint32_t off = (uint32_t)(nt * 8 + (lane & 7)) * APITCH + kcol;
                uint32_t kh0, kh1, kl0, kl1;
                ldsm_x2(buf + off, kh0, kh1);
                ldsm_x2(buf + ATILE + off, kl0, kl1);
                uint32_t bhK[2] = {kh0, kh1}, blK[2] = {kl0, kl1};
                mma_bf16(s[nt], qh[kb], bhK);
                mma_bf16(s[nt], ql[kb], bhK);
                mma_bf16(s[nt], qh[kb], blK);
            }
        }

        // scale + causal mask (diagonal tile only)
        bool diag = (jt == qt);
        #pragma unroll
        for (int nt = 0; nt < 8; nt++) {
            int colb = jt * 64 + nt * 8 + cql;
            #pragma unroll
            for (int q = 0; q < 4; q++) {
                float v = s[nt][q] * 0.125f;
                if (diag) {
                    int col = colb + (q & 1);
                    int row = r0g + (q >> 1) * 8;
                    if (col > row) v = -1e30f;
                }
                s[nt][q] = v;
            }
        }

        // ---- online softmax ----
        float mx0 = -1e30f, mx1 = -1e30f;
        #pragma unroll
        for (int nt = 0; nt < 8; nt++) {
            mx0 = fmaxf(mx0, fmaxf(s[nt][0], s[nt][1]));
            mx1 = fmaxf(mx1, fmaxf(s[nt][2], s[nt][3]));
        }
        mx0 = fmaxf(mx0, __shfl_xor_sync(0xffffffffu, mx0, 1));
        mx0 = fmaxf(mx0, __shfl_xor_sync(0xffffffffu, mx0, 2));
        mx1 = fmaxf(mx1, __shfl_xor_sync(0xffffffffu, mx1, 1));
        mx1 = fmaxf(mx1, __shfl_xor_sync(0xffffffffu, mx1, 2));
        float mn0 = fmaxf(mrow[0], mx0), mn1 = fmaxf(mrow[1], mx1);
        float sum0 = 0.f, sum1 = 0.f;
        #pragma unroll
        for (int nt = 0; nt < 8; nt++) {
            s[nt][0] = __expf(s[nt][0] - mn0);
            s[nt][1] = __expf(s[nt][1] - mn0);
            s[nt][2] = __expf(s[nt][2] - mn1);
            s[nt][3] = __expf(s[nt][3] - mn1);
            sum0 += s[nt][0] + s[nt][1];
            sum1 += s[nt][2] + s[nt][3];
        }
        sum0 += __shfl_xor_sync(0xffffffffu, sum0, 1);
        sum0 += __shfl_xor_sync(0xffffffffu, sum0, 2);
        sum1 += __shfl_xor_sync(0xffffffffu, sum1, 1);
        sum1 += __shfl_xor_sync(0xffffffffu, sum1, 2);
        float a0 = __expf(mrow[0] - mn0), a1 = __expf(mrow[1] - mn1);
        lrow[0] = lrow[0] * a0 + sum0;
        lrow[1] = lrow[1] * a1 + sum1;
        mrow[0] = mn0; mrow[1] = mn1;
        #pragma unroll
        for (int nt = 0; nt < 8; nt++) {
            oacc[nt][0] *= a0; oacc[nt][1] *= a0;
            oacc[nt][2] *= a1; oacc[nt][3] *= a1;
        }

        // ---- O += P V (3-term split), V frags via ldmatrix.trans ----
        uint32_t vbase = buf + 2 * ATILE;
        #pragma unroll
        for (int kb = 0; kb < 4; kb++) {
            // repack P C-frags (tiles 2kb, 2kb+1) into A-frag hi/lo
            uint32_t ph[4], pl[4];
            {
                float h0, l0, h1, l1;
                split_bf(s[2*kb][0], h0, l0); split_bf(s[2*kb][1], h1, l1);
                ph[0] = pack_bf2(h0, h1); pl[0] = pack_bf2(l0, l1);
                split_bf(s[2*kb][2], h0, l0); split_bf(s[2*kb][3], h1, l1);
                ph[1] = pack_bf2(h0, h1); pl[1] = pack_bf2(l0, l1);
                split_bf(s[2*kb+1][0], h0, l0); split_bf(s[2*kb+1][1], h1, l1);
                ph[2] = pack_bf2(h0, h1); pl[2] = pack_bf2(l0, l1);
                split_bf(s[2*kb+1][2], h0, l0); split_bf(s[2*kb+1][3], h1, l1);
                ph[3] = pack_bf2(h0, h1); pl[3] = pack_bf2(l0, l1);
            }
            uint32_t vrow = (uint32_t)(kb * 16 + (lane & 15)) * APITCH;
            #pragma unroll
            for (int nt = 0; nt < 8; nt++) {
                uint32_t off = vrow + nt * 16;
                uint32_t vh0, vh1, vl0, vl1;
                ldsm_x2t(vbase + off, vh0, vh1);
                ldsm_x2t(vbase + ATILE + off, vl0, vl1);
                uint32_t bhV[2] = {vh0, vh1}, blV[2] = {vl0, vl1};
                mma_bf16(oacc[nt], ph, bhV);
                mma_bf16(oacc[nt], pl, bhV);
                mma_bf16(oacc[nt], ph, blV);
            }
        }

        CP_WAIT0();
        __syncthreads();
    }

    // epilogue
    float li0 = 1.f / lrow[0], li1 = 1.f / lrow[1];
    size_t orow0 = (size_t)(b * TT + r0g) * DD + h * DHH;
    #pragma unroll
    for (int nt = 0; nt < 8; nt++) {
        int gc = nt * 8 + cql;
        float v0 = oacc[nt][0] * li0, v1 = oacc[nt][1] * li0;
        float v2 = oacc[nt][2] * li1, v3 = oacc[nt][3] * li1;
        float h0, l0, h1, l1;
        split_bf(v0, h0, l0); split_bf(v1, h1, l1);
        *(uint32_t*)&o_hi[orow0 + gc] = pack_bf2(h0, h1);
        *(uint32_t*)&o_lo[orow0 + gc] = pack_bf2(l0, l1);
        split_bf(v2, h0, l0); split_bf(v3, h1, l1);
        *(uint32_t*)&o_hi[orow0 + 8 * DD + gc] = pack_bf2(h0, h1);
        *(uint32_t*)&o_lo[orow0 + 8 * DD + gc] = pack_bf2(l0, l1);
    }
}

// ---------------- launcher ---------------------------------------------------
extern "C" void kernel_launch(void* const* d_in, const int* in_sizes, int n_in,
                              void* d_out, int out_size)
{
    const int*   ids  = (const int*)  d_in[0];
    const float* tok  = (const float*)d_in[1];
    const float* pos  = (const float*)d_in[2];
    const float* ln1s = (const float*)d_in[3];
    const float* ln1b = (const float*)d_in[4];
    const float* Wqkv = (const float*)d_in[5];
    const float* Wout = (const float*)d_in[6];
    const float* ln2s = (const float*)d_in[7];
    const float* ln2b = (const float*)d_in[8];
    const float* W1   = (const float*)d_in[9];
    const float* W2   = (const float*)d_in[10];
    const float* lnfs = (const float*)d_in[11];
    const float* lnfb = (const float*)d_in[12];
    float* out = (float*)d_out;

    float *x;
    __nv_bfloat16 *h_hi, *h_lo, *qkv_hi, *qkv_lo, *o_hi, *o_lo, *a_hi, *a_lo;
    __nv_bfloat16 *wqT_hi, *wqT_lo, *woT_hi, *woT_lo, *w1T_hi, *w1T_lo, *w2T_hi, *w2T_lo;
    cudaGetSymbolAddress((void**)&x,      g_x);
    cudaGetSymbolAddress((void**)&h_hi,   g_h_hi);
    cudaGetSymbolAddress((void**)&h_lo,   g_h_lo);
    cudaGetSymbolAddress((void**)&qkv_hi, g_qkv_hi);
    cudaGetSymbolAddress((void**)&qkv_lo, g_qkv_lo);
    cudaGetSymbolAddress((void**)&o_hi,   g_o_hi);
    cudaGetSymbolAddress((void**)&o_lo,   g_o_lo);
    cudaGetSymbolAddress((void**)&a_hi,   g_a_hi);
    cudaGetSymbolAddress((void**)&a_lo,   g_a_lo);
    cudaGetSymbolAddress((void**)&wqT_hi, g_WqkvT_hi);
    cudaGetSymbolAddress((void**)&wqT_lo, g_WqkvT_lo);
    cudaGetSymbolAddress((void**)&woT_hi, g_WoutT_hi);
    cudaGetSymbolAddress((void**)&woT_lo, g_WoutT_lo);
    cudaGetSymbolAddress((void**)&w1T_hi, g_W1T_hi);
    cudaGetSymbolAddress((void**)&w1T_lo, g_W1T_lo);
    cudaGetSymbolAddress((void**)&w2T_hi, g_W2T_hi);
    cudaGetSymbolAddress((void**)&w2T_lo, g_W2T_lo);

    cudaFuncSetAttribute(attn_mma,
                         cudaFuncAttributeMaxDynamicSharedMemorySize, ATTN_SMEM);
    cudaFuncSetAttribute(gemm_mma<1>,
                         cudaFuncAttributeMaxDynamicSharedMemorySize, GSM_TOTAL);
    cudaFuncSetAttribute(gemm_mma<2>,
                         cudaFuncAttributeMaxDynamicSharedMemorySize, GSM_TOTAL);
    cudaFuncSetAttribute(gemm_mma<3>,
                         cudaFuncAttributeMaxDynamicSharedMemorySize, GSM_TOTAL);

    dim3 tb(32, 8);
    for (int l = 0; l < LL; l++) {
        twk<<<dim3(D3 / 32, DD / 32), tb>>>(
            Wqkv + (size_t)l * DD * D3,
            wqT_hi + (size_t)l * D3 * DD, wqT_lo + (size_t)l * D3 * DD, DD, D3);
        twk<<<dim3(DD / 32, DD / 32), tb>>>(
            Wout + (size_t)l * DD * DD,
            woT_hi + (size_t)l * DD * DD, woT_lo + (size_t)l * DD * DD, DD, DD);
        twk<<<dim3(DFFF / 32, DD / 32), tb>>>(
            W1 + (size_t)l * DD * DFFF,
            w1T_hi + (size_t)l * DFFF * DD, w1T_lo + (size_t)l * DFFF * DD, DD, DFFF);
        twk<<<dim3(DD / 32, DFFF / 32), tb>>>(
            W2 + (size_t)l * DFFF * DD,
            w2T_hi + (size_t)l * DD * DFFF, w2T_lo + (size_t)l * DD * DFFF, DFFF, DD);
    }

    embed_kernel<<<(MROWS * DD + 255) / 256, 256>>>(ids, tok, pos, x);

    for (int l = 0; l < LL; l++) {
        ln_kernel<true><<<MROWS, 256>>>(x, ln1s + (size_t)l * DD, ln1b + (size_t)l * DD,
                                        nullptr, h_hi, h_lo);
        gemm_mma<3><<<dim3(D3 / 128, MROWS / 128), 256, GSM_TOTAL>>>(
            h_hi, h_lo,
            wqT_hi + (size_t)l * D3 * DD, wqT_lo + (size_t)l * D3 * DD,
            nullptr, nullptr, qkv_hi, qkv_lo, MROWS, D3, DD);
        attn_mma<<<dim3(TT / 64, BB * HH), 128, ATTN_SMEM>>>(qkv_hi, qkv_lo, o_hi, o_lo);
        gemm_mma<1><<<dim3(DD / 128, MROWS / 128), 256, GSM_TOTAL>>>(
            o_hi, o_lo,
            woT_hi + (size_t)l * DD * DD, woT_lo + (size_t)l * DD * DD,
            x, x, nullptr, nullptr, MROWS, DD, DD);
        ln_kernel<true><<<MROWS, 256>>>(x, ln2s + (size_t)l * DD, ln2b + (size_t)l * DD,
                                        nullptr, h_hi, h_lo);
        gemm_mma<2><<<dim3(DFFF / 128, MROWS / 128), 256, GSM_TOTAL>>>(
            h_hi, h_lo,
            w1T_hi + (size_t)l * DFFF * DD, w1T_lo + (size_t)l * DFFF * DD,
            nullptr, nullptr, a_hi, a_lo, MROWS, DFFF, DD);
        gemm_mma<1><<<dim3(DD / 128, MROWS / 128), 256, GSM_TOTAL>>>(
            a_hi, a_lo,
            w2T_hi + (size_t)l * DD * DFFF, w2T_lo + (size_t)l * DD * DFFF,
            x, x, nullptr, nullptr, MROWS, DD, DFFF);
    }

    ln_kernel<false><<<MROWS, 256>>>(x, lnfs, lnfb, out, nullptr, nullptr);
}